// round 7
// baseline (speedup 1.0000x reference)
#include <cuda_runtime.h>
#include <cuda_bf16.h>

// ---------------- problem constants ----------------
#define ZD 21
#define YD 256
#define XD 256
#define BD 2
#define CIN 16
#define C1 32
#define C2 64
#define GRID_SZ (BD * ZD * YD * XD)   // 2,752,512
#define N_MAX 400000
#define BN_EPS 1e-3f

#define V1 8      // voxels per warp, conv1
#define V2 16     // voxels per warp, conv2

typedef unsigned long long u64;

// ---------------- device scratch ----------------
__device__ int   g_grid[GRID_SZ];
__device__ float g_f1[N_MAX * C1];

// ---------------- helpers ----------------
__device__ __forceinline__ u64 pack2(float a, float b) {
    u64 r; asm("mov.b64 %0, {%1, %2};" : "=l"(r) : "f"(a), "f"(b)); return r;
}
__device__ __forceinline__ void ffma2(u64& acc, u64 a, u64 b) {
    asm("fma.rn.f32x2 %0, %1, %2, %0;" : "+l"(acc) : "l"(a), "l"(b));
}
__device__ __forceinline__ float2 unpack2(u64 p) {
    float2 r; asm("mov.b64 {%0, %1}, %2;" : "=f"(r.x), "=f"(r.y) : "l"(p)); return r;
}
__device__ __forceinline__ float bn_relu(float x, float g, float b, float m, float v) {
    float r = (x - m) * (g * rsqrtf(v + BN_EPS)) + b;
    return r > 0.0f ? r : 0.0f;
}

__global__ void reset_grid_kernel() {
    int i = blockIdx.x * blockDim.x + threadIdx.x;
    if (i < GRID_SZ) g_grid[i] = -1;
}

__global__ void scatter_kernel(const int* __restrict__ coors, int n) {
    int i = blockIdx.x * blockDim.x + threadIdx.x;
    if (i >= n) return;
    int4 c = ((const int4*)coors)[i];
    int lin = ((c.x * ZD + c.y) * YD + c.z) * XD + c.w;
    g_grid[lin] = i;
}

// ===================== conv1: SubMConv3d k=3 pad=1, 16 -> 32 =====================
// One warp handles V1 voxels. Lane l owns output channel l.
// Packed FFMA2: acc = (sum over even cc, sum over odd cc); features load as
// packed ulonglong2 directly (zero packing cost); weights packed once per warp.
__global__ void __launch_bounds__(256)
conv1_kernel(const float* __restrict__ feat,
             const int*   __restrict__ coors,
             const float* __restrict__ W1,
             const float* __restrict__ g1,
             const float* __restrict__ b1,
             const float* __restrict__ m1,
             const float* __restrict__ v1,
             int n) {
    int warp = blockIdx.x * (blockDim.x >> 5) + (threadIdx.x >> 5);
    int lane = threadIdx.x & 31;
    int base = warp * V1;
    if (base >= n) return;

    int idx[V1];
    unsigned uni = 0u;
#pragma unroll
    for (int v = 0; v < V1; v++) {
        int i = base + v;
        int id = -1;
        if (i < n && lane < 27) {
            int4 c = __ldg((const int4*)coors + i);
            int zz = c.y + lane / 9 - 1;
            int yy = c.z + (lane / 3) % 3 - 1;
            int xx = c.w + lane % 3 - 1;
            if (zz >= 0 && zz < ZD && yy >= 0 && yy < YD && xx >= 0 && xx < XD)
                id = g_grid[((c.x * ZD + zz) * YD + yy) * XD + xx];
        }
        idx[v] = id;
        uni |= __ballot_sync(0xffffffffu, id >= 0);
    }

    u64 acc[V1];
#pragma unroll
    for (int v = 0; v < V1; v++) acc[v] = 0ull;

    while (uni) {
        int k = __ffs(uni) - 1; uni &= uni - 1;
        int rows[V1];
#pragma unroll
        for (int v = 0; v < V1; v++) rows[v] = __shfl_sync(0xffffffffu, idx[v], k);

        // weights for offset k: pack (W[2p][lane], W[2p+1][lane]) — loaded once per warp
        const float* Wk = W1 + k * (CIN * C1);
        u64 w[8];
#pragma unroll
        for (int p = 0; p < 8; p++)
            w[p] = pack2(__ldg(Wk + (2 * p) * C1 + lane),
                         __ldg(Wk + (2 * p + 1) * C1 + lane));

#pragma unroll
        for (int v = 0; v < V1; v++) {
            if (rows[v] < 0) continue;                       // warp-uniform branch
            const ulonglong2* f = (const ulonglong2*)(feat + rows[v] * CIN);
            ulonglong2 qa = __ldg(f + 0);
            ulonglong2 qb = __ldg(f + 1);
            ulonglong2 qc = __ldg(f + 2);
            ulonglong2 qd = __ldg(f + 3);
            ffma2(acc[v], qa.x, w[0]); ffma2(acc[v], qa.y, w[1]);
            ffma2(acc[v], qb.x, w[2]); ffma2(acc[v], qb.y, w[3]);
            ffma2(acc[v], qc.x, w[4]); ffma2(acc[v], qc.y, w[5]);
            ffma2(acc[v], qd.x, w[6]); ffma2(acc[v], qd.y, w[7]);
        }
    }

    float gg = __ldg(g1 + lane), bb = __ldg(b1 + lane);
    float mm = __ldg(m1 + lane), vv = __ldg(v1 + lane);
#pragma unroll
    for (int v = 0; v < V1; v++) {
        int i = base + v;
        if (i >= n) break;
        float2 s = unpack2(acc[v]);
        g_f1[i * C1 + lane] = bn_relu(s.x + s.y, gg, bb, mm, vv);
    }
}

// ===================== conv2: SparseConv3d k=3 s=2 pad=(0,1,1), 32 -> 64 =========
// One warp handles V2 voxels. Lane l owns channel pair (2l, 2l+1):
// weights load as one contiguous u64 per cc (LDG.64, once per warp per k),
// feature scalar duplicated via mov.b64 (ALU pipe), FFMA2 on fma pipe.
__global__ void __launch_bounds__(128)
conv2_kernel(const int*   __restrict__ ocoors,
             const float* __restrict__ W2,
             const float* __restrict__ g2,
             const float* __restrict__ b2,
             const float* __restrict__ m2,
             const float* __restrict__ v2,
             float*       __restrict__ out,
             int m) {
    int warp = blockIdx.x * (blockDim.x >> 5) + (threadIdx.x >> 5);
    int lane = threadIdx.x & 31;
    int base = warp * V2;
    if (base >= m) return;

    int idx[V2];
    unsigned uni = 0u;
#pragma unroll
    for (int v = 0; v < V2; v++) {
        int i = base + v;
        int id = -1;
        if (i < m && lane < 27) {
            int4 c = __ldg((const int4*)ocoors + i);
            int zz = c.y * 2 + lane / 9;            // pad 0 in z
            int yy = c.z * 2 - 1 + (lane / 3) % 3;  // pad 1 in y
            int xx = c.w * 2 - 1 + lane % 3;        // pad 1 in x
            if (zz < ZD && yy >= 0 && yy < YD && xx >= 0 && xx < XD)
                id = g_grid[((c.x * ZD + zz) * YD + yy) * XD + xx];
        }
        idx[v] = id;
        uni |= __ballot_sync(0xffffffffu, id >= 0);
    }

    u64 acc[V2];
#pragma unroll
    for (int v = 0; v < V2; v++) acc[v] = 0ull;

    while (uni) {
        int k = __ffs(uni) - 1; uni &= uni - 1;
        int rows[V2];
#pragma unroll
        for (int v = 0; v < V2; v++) rows[v] = __shfl_sync(0xffffffffu, idx[v], k);

        const u64* Wk = (const u64*)(W2 + k * (C1 * C2)) + lane;   // ch pair (2l,2l+1)
#pragma unroll
        for (int ch = 0; ch < 4; ch++) {            // 8 input channels per chunk
            u64 w[8];
#pragma unroll
            for (int j = 0; j < 8; j++)
                w[j] = __ldg(Wk + (ch * 8 + j) * (C2 / 2));

#pragma unroll
            for (int v = 0; v < V2; v++) {
                if (rows[v] < 0) continue;          // warp-uniform branch
                const float4* f = (const float4*)(g_f1 + rows[v] * C1) + ch * 2;
                float4 fa = __ldg(f + 0);
                float4 fb = __ldg(f + 1);
                ffma2(acc[v], pack2(fa.x, fa.x), w[0]);
                ffma2(acc[v], pack2(fa.y, fa.y), w[1]);
                ffma2(acc[v], pack2(fa.z, fa.z), w[2]);
                ffma2(acc[v], pack2(fa.w, fa.w), w[3]);
                ffma2(acc[v], pack2(fb.x, fb.x), w[4]);
                ffma2(acc[v], pack2(fb.y, fb.y), w[5]);
                ffma2(acc[v], pack2(fb.z, fb.z), w[6]);
                ffma2(acc[v], pack2(fb.w, fb.w), w[7]);
            }
        }
    }

    float2 gg = __ldg((const float2*)g2 + lane);
    float2 bb = __ldg((const float2*)b2 + lane);
    float2 mm = __ldg((const float2*)m2 + lane);
    float2 vv = __ldg((const float2*)v2 + lane);
#pragma unroll
    for (int v = 0; v < V2; v++) {
        int i = base + v;
        if (i >= m) break;
        float2 s = unpack2(acc[v]);
        float2 o;
        o.x = bn_relu(s.x, gg.x, bb.x, mm.x, vv.x);
        o.y = bn_relu(s.y, gg.y, bb.y, mm.y, vv.y);
        ((float2*)(out + i * C2))[lane] = o;        // coalesced 256B store
    }
}

// Optional tail: if the harness flattens (f2, out_coors, batch_size) into d_out.
__global__ void tail_kernel(const int* __restrict__ ocoors,
                            const int* __restrict__ bs,
                            float* __restrict__ out,
                            int m, int extra) {
    int i = blockIdx.x * blockDim.x + threadIdx.x;
    if (i >= extra) return;
    float v;
    if (i < 4 * m)           v = (float)ocoors[i];
    else if (i == 4 * m)     v = (float)bs[0];
    else                     v = 0.0f;
    out[m * C2 + i] = v;
}

// ---------------- launch ----------------
extern "C" void kernel_launch(void* const* d_in, const int* in_sizes, int n_in,
                              void* d_out, int out_size) {
    const float* voxel_feat = (const float*)d_in[0];
    const int*   coors      = (const int*)  d_in[1];
    const int*   out_coors  = (const int*)  d_in[2];
    const float* W1 = (const float*)d_in[3];
    const float* g1 = (const float*)d_in[4];
    const float* b1 = (const float*)d_in[5];
    const float* m1 = (const float*)d_in[6];
    const float* v1 = (const float*)d_in[7];
    const float* W2 = (const float*)d_in[8];
    const float* g2 = (const float*)d_in[9];
    const float* b2 = (const float*)d_in[10];
    const float* m2 = (const float*)d_in[11];
    const float* v2 = (const float*)d_in[12];
    const int*   bs = (n_in > 13) ? (const int*)d_in[13] : nullptr;

    int n = in_sizes[0] / CIN;      // active input voxels
    int m = in_sizes[2] / 4;        // active output voxels
    float* out = (float*)d_out;

    reset_grid_kernel<<<(GRID_SZ + 255) / 256, 256>>>();
    scatter_kernel<<<(n + 255) / 256, 256>>>(coors, n);

    int w1 = (n + V1 - 1) / V1;                 // warps needed
    conv1_kernel<<<(w1 + 7) / 8, 256>>>(voxel_feat, coors, W1, g1, b1, m1, v1, n);

    int w2 = (m + V2 - 1) / V2;
    conv2_kernel<<<(w2 + 3) / 4, 128>>>(out_coors, W2, g2, b2, m2, v2, out, m);

    int extra = out_size - m * C2;
    if (extra > 0 && bs != nullptr) {
        tail_kernel<<<(extra + 255) / 256, 256>>>(out_coors, bs, out, m, extra);
    }
}

// round 10
// speedup vs baseline: 1.3918x; 1.3918x over previous
#include <cuda_runtime.h>
#include <cuda_bf16.h>

// ---------------- problem constants ----------------
#define ZD 21
#define YD 256
#define XD 256
#define BD 2
#define CIN 16
#define C1 32
#define C2 64
#define GRID_SZ (BD * ZD * YD * XD)   // 2,752,512
#define N_MAX 400000
#define BN_EPS 1e-3f

#define V1 4      // voxels per warp, conv1
#define V2 8      // voxels per warp, conv2

typedef unsigned long long u64;

// ---------------- device scratch ----------------
__device__ int   g_grid[GRID_SZ];
__device__ float g_f1[N_MAX * C1];

// ---------------- helpers ----------------
__device__ __forceinline__ u64 pack2(float a, float b) {
    u64 r; asm("mov.b64 %0, {%1, %2};" : "=l"(r) : "f"(a), "f"(b)); return r;
}
__device__ __forceinline__ void ffma2(u64& acc, u64 a, u64 b) {
    asm("fma.rn.f32x2 %0, %1, %2, %0;" : "+l"(acc) : "l"(a), "l"(b));
}
__device__ __forceinline__ float2 unpack2(u64 p) {
    float2 r; asm("mov.b64 {%0, %1}, %2;" : "=f"(r.x), "=f"(r.y) : "l"(p)); return r;
}
__device__ __forceinline__ float bn_relu(float x, float g, float b, float m, float v) {
    float r = (x - m) * (g * rsqrtf(v + BN_EPS)) + b;
    return r > 0.0f ? r : 0.0f;
}

__global__ void reset_grid_kernel() {
    int i = blockIdx.x * blockDim.x + threadIdx.x;
    if (i < GRID_SZ) g_grid[i] = -1;
}

__global__ void scatter_kernel(const int* __restrict__ coors, int n) {
    int i = blockIdx.x * blockDim.x + threadIdx.x;
    if (i >= n) return;
    int4 c = ((const int4*)coors)[i];
    int lin = ((c.x * ZD + c.y) * YD + c.z) * XD + c.w;
    g_grid[lin] = i;
}

// ===================== conv1: SubMConv3d k=3 pad=1, 16 -> 32 =====================
// One warp handles V1 voxels. Lane l owns output channel l.
// acc (lo,hi) = partial sums over (even cc, odd cc); features load as packed
// ulonglong2 (zero pack cost); weights packed once per warp per offset.
__global__ void __launch_bounds__(256)
conv1_kernel(const float* __restrict__ feat,
             const int*   __restrict__ coors,
             const float* __restrict__ W1,
             const float* __restrict__ g1,
             const float* __restrict__ b1,
             const float* __restrict__ m1,
             const float* __restrict__ v1,
             int n) {
    int warp = blockIdx.x * (blockDim.x >> 5) + (threadIdx.x >> 5);
    int lane = threadIdx.x & 31;
    int base = warp * V1;
    if (base >= n) return;

    int idx[V1];
    unsigned uni = 0u;
#pragma unroll
    for (int v = 0; v < V1; v++) {
        int i = base + v;
        int id = -1;
        if (i < n && lane < 27) {
            int4 c = __ldg((const int4*)coors + i);
            int zz = c.y + lane / 9 - 1;
            int yy = c.z + (lane / 3) % 3 - 1;
            int xx = c.w + lane % 3 - 1;
            if (zz >= 0 && zz < ZD && yy >= 0 && yy < YD && xx >= 0 && xx < XD)
                id = g_grid[((c.x * ZD + zz) * YD + yy) * XD + xx];
        }
        idx[v] = id;
        uni |= __ballot_sync(0xffffffffu, id >= 0);
    }

    u64 acc[V1];
#pragma unroll
    for (int v = 0; v < V1; v++) acc[v] = 0ull;

    while (uni) {
        int k = __ffs(uni) - 1; uni &= uni - 1;

        // pack weights for offset k: w[p] = (W[2p][lane], W[2p+1][lane])
        const float* Wk = W1 + k * (CIN * C1);
        u64 w[8];
#pragma unroll
        for (int p = 0; p < 8; p++)
            w[p] = pack2(__ldg(Wk + (2 * p) * C1 + lane),
                         __ldg(Wk + (2 * p + 1) * C1 + lane));

#pragma unroll
        for (int v = 0; v < V1; v++) {
            int row = __shfl_sync(0xffffffffu, idx[v], k);
            if (row < 0) continue;                      // warp-uniform branch
            const ulonglong2* f = (const ulonglong2*)(feat + row * CIN);
            ulonglong2 qa = __ldg(f + 0);
            ulonglong2 qb = __ldg(f + 1);
            ulonglong2 qc = __ldg(f + 2);
            ulonglong2 qd = __ldg(f + 3);
            ffma2(acc[v], qa.x, w[0]); ffma2(acc[v], qa.y, w[1]);
            ffma2(acc[v], qb.x, w[2]); ffma2(acc[v], qb.y, w[3]);
            ffma2(acc[v], qc.x, w[4]); ffma2(acc[v], qc.y, w[5]);
            ffma2(acc[v], qd.x, w[6]); ffma2(acc[v], qd.y, w[7]);
        }
    }

    float gg = __ldg(g1 + lane), bb = __ldg(b1 + lane);
    float mm = __ldg(m1 + lane), vv = __ldg(v1 + lane);
#pragma unroll
    for (int v = 0; v < V1; v++) {
        int i = base + v;
        if (i >= n) break;
        float2 s = unpack2(acc[v]);
        g_f1[i * C1 + lane] = bn_relu(s.x + s.y, gg, bb, mm, vv);
    }
}

// ===================== conv2: SparseConv3d k=3 s=2 pad=(0,1,1), 32 -> 64 =========
// One warp handles V2 voxels. Lane l owns channels {l, l+32}.
// accA/accB (lo,hi) = (even cc, odd cc) partial sums -> features load packed,
// NO packing instructions in the per-voxel hot loop. Weights packed per warp
// per offset in chunks of 8 cc (keeps live registers bounded).
__global__ void __launch_bounds__(128)
conv2_kernel(const int*   __restrict__ ocoors,
             const float* __restrict__ W2,
             const float* __restrict__ g2,
             const float* __restrict__ b2,
             const float* __restrict__ m2,
             const float* __restrict__ v2,
             float*       __restrict__ out,
             int m) {
    int warp = blockIdx.x * (blockDim.x >> 5) + (threadIdx.x >> 5);
    int lane = threadIdx.x & 31;
    int base = warp * V2;
    if (base >= m) return;

    int idx[V2];
    unsigned uni = 0u;
#pragma unroll
    for (int v = 0; v < V2; v++) {
        int i = base + v;
        int id = -1;
        if (i < m && lane < 27) {
            int4 c = __ldg((const int4*)ocoors + i);
            int zz = c.y * 2 + lane / 9;            // pad 0 in z
            int yy = c.z * 2 - 1 + (lane / 3) % 3;  // pad 1 in y
            int xx = c.w * 2 - 1 + lane % 3;        // pad 1 in x
            if (zz < ZD && yy >= 0 && yy < YD && xx >= 0 && xx < XD)
                id = g_grid[((c.x * ZD + zz) * YD + yy) * XD + xx];
        }
        idx[v] = id;
        uni |= __ballot_sync(0xffffffffu, id >= 0);
    }

    u64 accA[V2], accB[V2];
#pragma unroll
    for (int v = 0; v < V2; v++) { accA[v] = 0ull; accB[v] = 0ull; }

    while (uni) {
        int k = __ffs(uni) - 1; uni &= uni - 1;
        int rows[V2];
#pragma unroll
        for (int v = 0; v < V2; v++) rows[v] = __shfl_sync(0xffffffffu, idx[v], k);

        const float* Wk = W2 + k * (C1 * C2);
#pragma unroll
        for (int ch = 0; ch < 4; ch++) {            // 8 input channels per chunk
            // weight pairs for cc = 8ch+2p, 8ch+2p+1 ; channels lane and lane+32
            u64 wA[4], wB[4];
#pragma unroll
            for (int p = 0; p < 4; p++) {
                int cc0 = ch * 8 + 2 * p;
                const float* w0 = Wk + cc0 * C2;
                const float* w1 = Wk + (cc0 + 1) * C2;
                wA[p] = pack2(__ldg(w0 + lane),      __ldg(w1 + lane));
                wB[p] = pack2(__ldg(w0 + lane + 32), __ldg(w1 + lane + 32));
            }
#pragma unroll
            for (int v = 0; v < V2; v++) {
                int row = rows[v];
                if (row < 0) continue;              // warp-uniform branch
                const ulonglong2* f = (const ulonglong2*)(g_f1 + row * C1) + ch * 2;
                ulonglong2 qa = __ldg(f + 0);       // cc 8ch .. 8ch+3 (packed pairs)
                ulonglong2 qb = __ldg(f + 1);       // cc 8ch+4 .. 8ch+7
                ffma2(accA[v], qa.x, wA[0]); ffma2(accB[v], qa.x, wB[0]);
                ffma2(accA[v], qa.y, wA[1]); ffma2(accB[v], qa.y, wB[1]);
                ffma2(accA[v], qb.x, wA[2]); ffma2(accB[v], qb.x, wB[2]);
                ffma2(accA[v], qb.y, wA[3]); ffma2(accB[v], qb.y, wB[3]);
            }
        }
    }

    float ga = __ldg(g2 + lane),      ba = __ldg(b2 + lane);
    float ma = __ldg(m2 + lane),      va = __ldg(v2 + lane);
    float gb = __ldg(g2 + lane + 32), bb = __ldg(b2 + lane + 32);
    float mb = __ldg(m2 + lane + 32), vb = __ldg(v2 + lane + 32);
#pragma unroll
    for (int v = 0; v < V2; v++) {
        int i = base + v;
        if (i >= m) break;
        float2 sA = unpack2(accA[v]);
        float2 sB = unpack2(accB[v]);
        out[i * C2 + lane]      = bn_relu(sA.x + sA.y, ga, ba, ma, va);
        out[i * C2 + lane + 32] = bn_relu(sB.x + sB.y, gb, bb, mb, vb);
    }
}

// Optional tail: if the harness flattens (f2, out_coors, batch_size) into d_out.
__global__ void tail_kernel(const int* __restrict__ ocoors,
                            const int* __restrict__ bs,
                            float* __restrict__ out,
                            int m, int extra) {
    int i = blockIdx.x * blockDim.x + threadIdx.x;
    if (i >= extra) return;
    float v;
    if (i < 4 * m)           v = (float)ocoors[i];
    else if (i == 4 * m)     v = (float)bs[0];
    else                     v = 0.0f;
    out[m * C2 + i] = v;
}

// ---------------- launch ----------------
extern "C" void kernel_launch(void* const* d_in, const int* in_sizes, int n_in,
                              void* d_out, int out_size) {
    const float* voxel_feat = (const float*)d_in[0];
    const int*   coors      = (const int*)  d_in[1];
    const int*   out_coors  = (const int*)  d_in[2];
    const float* W1 = (const float*)d_in[3];
    const float* g1 = (const float*)d_in[4];
    const float* b1 = (const float*)d_in[5];
    const float* m1 = (const float*)d_in[6];
    const float* v1 = (const float*)d_in[7];
    const float* W2 = (const float*)d_in[8];
    const float* g2 = (const float*)d_in[9];
    const float* b2 = (const float*)d_in[10];
    const float* m2 = (const float*)d_in[11];
    const float* v2 = (const float*)d_in[12];
    const int*   bs = (n_in > 13) ? (const int*)d_in[13] : nullptr;

    int n = in_sizes[0] / CIN;      // active input voxels
    int m = in_sizes[2] / 4;        // active output voxels
    float* out = (float*)d_out;

    reset_grid_kernel<<<(GRID_SZ + 255) / 256, 256>>>();
    scatter_kernel<<<(n + 255) / 256, 256>>>(coors, n);

    int w1 = (n + V1 - 1) / V1;                 // warps needed
    conv1_kernel<<<(w1 + 7) / 8, 256>>>(voxel_feat, coors, W1, g1, b1, m1, v1, n);

    int w2 = (m + V2 - 1) / V2;
    conv2_kernel<<<(w2 + 3) / 4, 128>>>(out_coors, W2, g2, b2, m2, v2, out, m);

    int extra = out_size - m * C2;
    if (extra > 0 && bs != nullptr) {
        tail_kernel<<<(extra + 255) / 256, 256>>>(out_coors, bs, out, m, extra);
    }
}

// round 15
// speedup vs baseline: 1.8239x; 1.3105x over previous
#include <cuda_runtime.h>
#include <cuda_bf16.h>

// ---------------- problem constants ----------------
#define ZD 21
#define YD 256
#define XD 256
#define BD 2
#define CIN 16
#define C1 32
#define C2 64
#define GRID_SZ (BD * ZD * YD * XD)   // 2,752,512
#define N_MAX 400000
#define BN_EPS 1e-3f

#define V1 4      // voxels per warp, conv1
#define V2 4      // voxels per warp, conv2

typedef unsigned long long u64;

// ---------------- device scratch ----------------
__device__ int   g_grid[GRID_SZ];
__device__ float g_f1[N_MAX * C1];
__device__ u64   g_W1p[27 * 8 * 32];    // (W1[k][2p][ch], W1[k][2p+1][ch])
__device__ u64   g_W2p[27 * 16 * 64];   // (W2[k][2p][ch], W2[k][2p+1][ch])

// ---------------- helpers ----------------
__device__ __forceinline__ u64 pack2(float a, float b) {
    u64 r; asm("mov.b64 %0, {%1, %2};" : "=l"(r) : "f"(a), "f"(b)); return r;
}
__device__ __forceinline__ void ffma2(u64& acc, u64 a, u64 b) {
    asm("fma.rn.f32x2 %0, %1, %2, %0;" : "+l"(acc) : "l"(a), "l"(b));
}
__device__ __forceinline__ float2 unpack2(u64 p) {
    float2 r; asm("mov.b64 {%0, %1}, %2;" : "=f"(r.x), "=f"(r.y) : "l"(p)); return r;
}
__device__ __forceinline__ float bn_relu(float x, float g, float b, float m, float v) {
    float r = (x - m) * (g * rsqrtf(v + BN_EPS)) + b;
    return r > 0.0f ? r : 0.0f;
}

__global__ void reset_grid_kernel() {
    int i = blockIdx.x * blockDim.x + threadIdx.x;
    if (i < GRID_SZ / 4) ((int4*)g_grid)[i] = make_int4(-1, -1, -1, -1);
}

__global__ void scatter_kernel(const int* __restrict__ coors, int n) {
    int i = blockIdx.x * blockDim.x + threadIdx.x;
    if (i >= n) return;
    int4 c = ((const int4*)coors)[i];
    int lin = ((c.x * ZD + c.y) * YD + c.z) * XD + c.w;
    g_grid[lin] = i;
}

// Pre-pack weights into cc-pair u64 layout (runs once per launch, ~3us).
__global__ void prep_w1_kernel(const float* __restrict__ W1) {
    int i = blockIdx.x * blockDim.x + threadIdx.x;  // 27*8*32 = 6912
    if (i >= 27 * 8 * 32) return;
    int ch = i & 31, p = (i >> 5) & 7, k = i >> 8;
    const float* base = W1 + k * (CIN * C1);
    g_W1p[i] = pack2(base[(2 * p) * C1 + ch], base[(2 * p + 1) * C1 + ch]);
}
__global__ void prep_w2_kernel(const float* __restrict__ W2) {
    int i = blockIdx.x * blockDim.x + threadIdx.x;  // 27*16*64 = 27648
    if (i >= 27 * 16 * 64) return;
    int ch = i & 63, p = (i >> 6) & 15, k = i >> 10;
    const float* base = W2 + k * (C1 * C2);
    g_W2p[i] = pack2(base[(2 * p) * C2 + ch], base[(2 * p + 1) * C2 + ch]);
}

// ===================== conv1: SubMConv3d k=3 pad=1, 16 -> 32 =====================
// One warp handles V1 voxels. Lane l owns output channel l.
// acc (lo,hi) = (even cc, odd cc) partial sums; features load packed as
// ulonglong2; weights are pre-packed u64, loaded once per warp per offset.
__global__ void __launch_bounds__(256)
conv1_kernel(const float* __restrict__ feat,
             const int*   __restrict__ coors,
             const float* __restrict__ g1,
             const float* __restrict__ b1,
             const float* __restrict__ m1,
             const float* __restrict__ v1,
             int n) {
    int warp = blockIdx.x * (blockDim.x >> 5) + (threadIdx.x >> 5);
    int lane = threadIdx.x & 31;
    int base = warp * V1;
    if (base >= n) return;

    int idx[V1];
    unsigned uni = 0u;
#pragma unroll
    for (int v = 0; v < V1; v++) {
        int i = base + v;
        int id = -1;
        if (i < n && lane < 27) {
            int4 c = __ldg((const int4*)coors + i);
            int zz = c.y + lane / 9 - 1;
            int yy = c.z + (lane / 3) % 3 - 1;
            int xx = c.w + lane % 3 - 1;
            if (zz >= 0 && zz < ZD && yy >= 0 && yy < YD && xx >= 0 && xx < XD)
                id = g_grid[((c.x * ZD + zz) * YD + yy) * XD + xx];
        }
        idx[v] = id;
        uni |= __ballot_sync(0xffffffffu, id >= 0);
    }

    u64 acc[V1];
#pragma unroll
    for (int v = 0; v < V1; v++) acc[v] = 0ull;

    while (uni) {
        int k = __ffs(uni) - 1; uni &= uni - 1;

        const u64* Wk = g_W1p + k * (8 * 32) + lane;
        u64 w[8];
#pragma unroll
        for (int p = 0; p < 8; p++) w[p] = __ldg(Wk + p * 32);

#pragma unroll
        for (int v = 0; v < V1; v++) {
            int row = __shfl_sync(0xffffffffu, idx[v], k);
            if (row < 0) continue;                      // warp-uniform branch
            const ulonglong2* f = (const ulonglong2*)(feat + row * CIN);
            ulonglong2 qa = __ldg(f + 0);
            ulonglong2 qb = __ldg(f + 1);
            ulonglong2 qc = __ldg(f + 2);
            ulonglong2 qd = __ldg(f + 3);
            ffma2(acc[v], qa.x, w[0]); ffma2(acc[v], qa.y, w[1]);
            ffma2(acc[v], qb.x, w[2]); ffma2(acc[v], qb.y, w[3]);
            ffma2(acc[v], qc.x, w[4]); ffma2(acc[v], qc.y, w[5]);
            ffma2(acc[v], qd.x, w[6]); ffma2(acc[v], qd.y, w[7]);
        }
    }

    float gg = __ldg(g1 + lane), bb = __ldg(b1 + lane);
    float mm = __ldg(m1 + lane), vv = __ldg(v1 + lane);
#pragma unroll
    for (int v = 0; v < V1; v++) {
        int i = base + v;
        if (i >= n) break;
        float2 s = unpack2(acc[v]);
        g_f1[i * C1 + lane] = bn_relu(s.x + s.y, gg, bb, mm, vv);
    }
}

// ===================== conv2: SparseConv3d k=3 s=2 pad=(0,1,1), 32 -> 64 =========
// One warp handles V2 voxels. Lane l owns channels {l, l+32}.
// accA/accB (lo,hi) = (even cc, odd cc) partial sums; features load packed,
// weights are pre-packed u64 loaded per warp per offset in 4 chunks.
__global__ void __launch_bounds__(256)
conv2_kernel(const int*   __restrict__ ocoors,
             const float* __restrict__ g2,
             const float* __restrict__ b2,
             const float* __restrict__ m2,
             const float* __restrict__ v2,
             float*       __restrict__ out,
             int m) {
    int warp = blockIdx.x * (blockDim.x >> 5) + (threadIdx.x >> 5);
    int lane = threadIdx.x & 31;
    int base = warp * V2;
    if (base >= m) return;

    int idx[V2];
    unsigned uni = 0u;
#pragma unroll
    for (int v = 0; v < V2; v++) {
        int i = base + v;
        int id = -1;
        if (i < m && lane < 27) {
            int4 c = __ldg((const int4*)ocoors + i);
            int zz = c.y * 2 + lane / 9;            // pad 0 in z
            int yy = c.z * 2 - 1 + (lane / 3) % 3;  // pad 1 in y
            int xx = c.w * 2 - 1 + lane % 3;        // pad 1 in x
            if (zz < ZD && yy >= 0 && yy < YD && xx >= 0 && xx < XD)
                id = g_grid[((c.x * ZD + zz) * YD + yy) * XD + xx];
        }
        idx[v] = id;
        uni |= __ballot_sync(0xffffffffu, id >= 0);
    }

    u64 accA[V2], accB[V2];
#pragma unroll
    for (int v = 0; v < V2; v++) { accA[v] = 0ull; accB[v] = 0ull; }

    while (uni) {
        int k = __ffs(uni) - 1; uni &= uni - 1;
        int rows[V2];
#pragma unroll
        for (int v = 0; v < V2; v++) rows[v] = __shfl_sync(0xffffffffu, idx[v], k);

        const u64* Wk = g_W2p + k * (16 * 64);
#pragma unroll
        for (int ch = 0; ch < 4; ch++) {            // 4 cc-pairs (8 cc) per chunk
            u64 wA[4], wB[4];
#pragma unroll
            for (int p = 0; p < 4; p++) {
                const u64* wp = Wk + (ch * 4 + p) * 64;
                wA[p] = __ldg(wp + lane);
                wB[p] = __ldg(wp + lane + 32);
            }
#pragma unroll
            for (int v = 0; v < V2; v++) {
                int row = rows[v];
                if (row < 0) continue;              // warp-uniform branch
                const ulonglong2* f = (const ulonglong2*)(g_f1 + row * C1) + ch * 2;
                ulonglong2 qa = __ldg(f + 0);       // cc pairs 4ch, 4ch+1
                ulonglong2 qb = __ldg(f + 1);       // cc pairs 4ch+2, 4ch+3
                ffma2(accA[v], qa.x, wA[0]); ffma2(accB[v], qa.x, wB[0]);
                ffma2(accA[v], qa.y, wA[1]); ffma2(accB[v], qa.y, wB[1]);
                ffma2(accA[v], qb.x, wA[2]); ffma2(accB[v], qb.x, wB[2]);
                ffma2(accA[v], qb.y, wA[3]); ffma2(accB[v], qb.y, wB[3]);
            }
        }
    }

    float ga = __ldg(g2 + lane),      ba = __ldg(b2 + lane);
    float ma = __ldg(m2 + lane),      va = __ldg(v2 + lane);
    float gb = __ldg(g2 + lane + 32), bb = __ldg(b2 + lane + 32);
    float mb = __ldg(m2 + lane + 32), vb = __ldg(v2 + lane + 32);
#pragma unroll
    for (int v = 0; v < V2; v++) {
        int i = base + v;
        if (i >= m) break;
        float2 sA = unpack2(accA[v]);
        float2 sB = unpack2(accB[v]);
        out[i * C2 + lane]      = bn_relu(sA.x + sA.y, ga, ba, ma, va);
        out[i * C2 + lane + 32] = bn_relu(sB.x + sB.y, gb, bb, mb, vb);
    }
}

// Optional tail: if the harness flattens (f2, out_coors, batch_size) into d_out.
__global__ void tail_kernel(const int* __restrict__ ocoors,
                            const int* __restrict__ bs,
                            float* __restrict__ out,
                            int m, int extra) {
    int i = blockIdx.x * blockDim.x + threadIdx.x;
    if (i >= extra) return;
    float v;
    if (i < 4 * m)           v = (float)ocoors[i];
    else if (i == 4 * m)     v = (float)bs[0];
    else                     v = 0.0f;
    out[m * C2 + i] = v;
}

// ---------------- launch ----------------
extern "C" void kernel_launch(void* const* d_in, const int* in_sizes, int n_in,
                              void* d_out, int out_size) {
    const float* voxel_feat = (const float*)d_in[0];
    const int*   coors      = (const int*)  d_in[1];
    const int*   out_coors  = (const int*)  d_in[2];
    const float* W1 = (const float*)d_in[3];
    const float* g1 = (const float*)d_in[4];
    const float* b1 = (const float*)d_in[5];
    const float* m1 = (const float*)d_in[6];
    const float* v1 = (const float*)d_in[7];
    const float* W2 = (const float*)d_in[8];
    const float* g2 = (const float*)d_in[9];
    const float* b2 = (const float*)d_in[10];
    const float* m2 = (const float*)d_in[11];
    const float* v2 = (const float*)d_in[12];
    const int*   bs = (n_in > 13) ? (const int*)d_in[13] : nullptr;

    int n = in_sizes[0] / CIN;      // active input voxels
    int m = in_sizes[2] / 4;        // active output voxels
    float* out = (float*)d_out;

    reset_grid_kernel<<<(GRID_SZ / 4 + 255) / 256, 256>>>();
    scatter_kernel<<<(n + 255) / 256, 256>>>(coors, n);
    prep_w1_kernel<<<(27 * 8 * 32 + 255) / 256, 256>>>(W1);
    prep_w2_kernel<<<(27 * 16 * 64 + 255) / 256, 256>>>(W2);

    int w1 = (n + V1 - 1) / V1;                 // warps needed
    conv1_kernel<<<(w1 + 7) / 8, 256>>>(voxel_feat, coors, g1, b1, m1, v1, n);

    int w2 = (m + V2 - 1) / V2;
    conv2_kernel<<<(w2 + 7) / 8, 256>>>(out_coors, g2, b2, m2, v2, out, m);

    int extra = out_size - m * C2;
    if (extra > 0 && bs != nullptr) {
        tail_kernel<<<(extra + 255) / 256, 256>>>(out_coors, bs, out, m, extra);
    }
}